// round 13
// baseline (speedup 1.0000x reference)
#include <cuda_runtime.h>
#include <cuda_bf16.h>
#include <cstdint>

#define NN      50000
#define EE      800000
#define INDIM   256
#define HIDC    32
#define NHEADS  8
#define OUTDIM  64
#define C1      (NHEADS * HIDC)   // 256
#define NB      512               // total output cols of GEMM1 (Wl|Wr)
#define NB2     64                // total output cols of GEMM2 (W2l|W2r)
#define NEGSLOPE 0.2f

typedef unsigned long long u64;

// ---------------- scratch (device globals) ---------------------------------
__device__ float g_xl1[(size_t)NN * C1];
__device__ float g_xr1[(size_t)NN * C1];
__device__ float g_xl2[(size_t)NN * HIDC];
__device__ float g_xr2[(size_t)NN * HIDC];
__device__ int   g_deg   [NN];
__device__ int   g_rowptr[NN];
__device__ int   g_cursor[NN];
__device__ int   g_csrc  [EE];
__device__ int   g_bsums [256];
// bf16 split operands
__device__ __align__(16) __nv_bfloat16 g_Ah[(size_t)NN * INDIM];
__device__ __align__(16) __nv_bfloat16 g_Al[(size_t)NN * INDIM];
__device__ __align__(16) __nv_bfloat16 g_Bh[(size_t)NB * INDIM];
__device__ __align__(16) __nv_bfloat16 g_Bl[(size_t)NB * INDIM];
__device__ __align__(16) __nv_bfloat16 g_H1h[(size_t)NN * C1];   // h1 hi
__device__ __align__(16) __nv_bfloat16 g_H1l[(size_t)NN * C1];   // h1 lo
__device__ __align__(16) __nv_bfloat16 g_B2h[(size_t)NB2 * C1];
__device__ __align__(16) __nv_bfloat16 g_B2l[(size_t)NB2 * C1];

// ---------------- helpers ---------------------------------------------------
__device__ __forceinline__ float lrelu(float v) { return v > 0.f ? v : NEGSLOPE * v; }
__device__ __forceinline__ float elu(float v)   { return v > 0.f ? v : expm1f(v); }

__device__ __forceinline__ uint32_t smem_u32(const void* p)
{
    uint32_t a;
    asm("{ .reg .u64 t; cvta.to.shared.u64 t, %1; cvt.u32.u64 %0, t; }"
        : "=r"(a) : "l"(p));
    return a;
}

// bf16 tensor-core mma (sm_80+ base)
#define MMA_BF16(d, a0, a1, a2, a3, b0, b1)                                  \
    asm volatile(                                                            \
        "mma.sync.aligned.m16n8k16.row.col.f32.bf16.bf16.f32 "               \
        "{%0,%1,%2,%3}, {%4,%5,%6,%7}, {%8,%9}, {%0,%1,%2,%3};"              \
        : "+f"((d)[0]), "+f"((d)[1]), "+f"((d)[2]), "+f"((d)[3])             \
        : "r"(a0), "r"(a1), "r"(a2), "r"(a3), "r"(b0), "r"(b1))

// ldmatrix (sm_75+ base)
#define LDSM_X4(r0, r1, r2, r3, addr)                                        \
    asm volatile("ldmatrix.sync.aligned.m8n8.x4.shared.b16 {%0,%1,%2,%3}, [%4];" \
                 : "=r"(r0), "=r"(r1), "=r"(r2), "=r"(r3) : "r"(addr))

// cp.async (sm_80+ base)
#define CP16(dst_u32, src_ptr) \
    asm volatile("cp.async.cg.shared.global [%0], [%1], 16;" \
                 :: "r"(dst_u32), "l"(src_ptr))
#define CP_COMMIT() asm volatile("cp.async.commit_group;" ::: "memory")
#define CP_WAIT(n)  asm volatile("cp.async.wait_group %0;" :: "n"(n) : "memory")

// ---------------- conversion kernels -----------------------------------------
__global__ void conv_x_k(const float* __restrict__ x,
                         __nv_bfloat16* __restrict__ Ah,
                         __nv_bfloat16* __restrict__ Al)
{
    size_t i = (size_t)blockIdx.x * blockDim.x + threadIdx.x;
    if (i >= (size_t)NN * INDIM) return;
    float v = x[i];
    __nv_bfloat16 h = __float2bfloat16(v);
    Ah[i] = h;
    Al[i] = __float2bfloat16(v - __bfloat162float(h));
}

__global__ void conv_w_k(const float* __restrict__ W1l, const float* __restrict__ W1r,
                         __nv_bfloat16* __restrict__ Bh, __nv_bfloat16* __restrict__ Bl)
{
    int i = blockIdx.x * blockDim.x + threadIdx.x;
    if (i >= NB * INDIM) return;
    int n = i >> 8;
    int k = i & 255;
    float v = (n < C1) ? W1l[(size_t)k * C1 + n] : W1r[(size_t)k * C1 + (n - C1)];
    __nv_bfloat16 h = __float2bfloat16(v);
    Bh[i] = h;
    Bl[i] = __float2bfloat16(v - __bfloat162float(h));
}

__global__ void conv_w2_k(const float* __restrict__ W2l, const float* __restrict__ W2r,
                          __nv_bfloat16* __restrict__ B2h, __nv_bfloat16* __restrict__ B2l)
{
    int i = blockIdx.x * blockDim.x + threadIdx.x;
    if (i >= NB2 * C1) return;
    int n = i >> 8;          // 0..63
    int k = i & 255;
    float v = (n < HIDC) ? W2l[(size_t)k * HIDC + n]
                         : W2r[(size_t)k * HIDC + (n - HIDC)];
    __nv_bfloat16 h = __float2bfloat16(v);
    B2h[i] = h;
    B2l[i] = __float2bfloat16(v - __bfloat162float(h));
}

// ============================================================================
// GEMM1 via mma.sync bf16 3-product split, cp.async double-buffered, ldmatrix.
// ============================================================================
#define KCH    32
#define PAD2   40
#define T_ELEM (128 * PAD2)
#define T_BYTE (T_ELEM * 2)          // 10240
#define STG_BYTE (4 * T_BYTE)        // 40960
#define SMEM_BYTES (2 * STG_BYTE)    // 81920

__global__ __launch_bounds__(256)
void gemm1_mma(const __nv_bfloat16* __restrict__ Ah, const __nv_bfloat16* __restrict__ Al,
               const __nv_bfloat16* __restrict__ Bh, const __nv_bfloat16* __restrict__ Bl,
               const float* __restrict__ bl1, const float* __restrict__ br1,
               float* __restrict__ Xl, float* __restrict__ Xr)
{
    extern __shared__ __nv_bfloat16 sm[];
    const uint32_t smb = smem_u32(sm);

    const int tid  = threadIdx.x;
    const int wid  = tid >> 5;
    const int lane = tid & 31;
    const int wm   = wid & 1;
    const int wn   = wid >> 1;
    const int rowBase = blockIdx.y * 128;
    const int colBase = blockIdx.x * 128;

    const int lr = lane >> 2;
    const int lc = (lane & 3) * 2;

    const int aRowOff = lane & 15;
    const int aKOff   = (lane >> 4) * 8;
    const int bGrp    = lane >> 3;
    const int bRowOff = (lane & 7) + (bGrp >> 1) * 8;
    const int bKOff   = (bGrp & 1) * 8;

#define LOAD_STAGE(stg, kOff) do {                                            \
    uint32_t sb = smb + (stg) * STG_BYTE;                                     \
    for (int idx = tid; idx < 512; idx += 256) {                              \
        int r  = idx >> 2;                                                    \
        int k8 = (idx & 3) * 8;                                               \
        uint32_t soff = (uint32_t)(r * (PAD2 * 2) + k8 * 2);                  \
        int ga = min(rowBase + r, NN - 1);                                    \
        int gb = colBase + r;                                                 \
        CP16(sb + soff,              Ah + (size_t)ga * INDIM + (kOff) + k8);  \
        CP16(sb + T_BYTE + soff,     Al + (size_t)ga * INDIM + (kOff) + k8);  \
        CP16(sb + 2 * T_BYTE + soff, Bh + (size_t)gb * INDIM + (kOff) + k8);  \
        CP16(sb + 3 * T_BYTE + soff, Bl + (size_t)gb * INDIM + (kOff) + k8);  \
    }                                                                         \
} while (0)

    float acc[4][4][4];
#pragma unroll
    for (int i = 0; i < 4; i++)
#pragma unroll
        for (int j = 0; j < 4; j++)
#pragma unroll
            for (int f = 0; f < 4; f++) acc[i][j][f] = 0.f;

    LOAD_STAGE(0, 0);
    CP_COMMIT();

    for (int kc = 0; kc < 8; kc++) {
        const int stg = kc & 1;
        if (kc + 1 < 8) {
            LOAD_STAGE((kc + 1) & 1, (kc + 1) * KCH);
            CP_COMMIT();
            CP_WAIT(1);
        } else {
            CP_WAIT(0);
        }
        __syncthreads();

        const uint32_t sAh_u = smb + stg * STG_BYTE;
        const uint32_t sAl_u = sAh_u + T_BYTE;
        const uint32_t sBh_u = sAh_u + 2 * T_BYTE;
        const uint32_t sBl_u = sAh_u + 3 * T_BYTE;

#pragma unroll
        for (int ks = 0; ks < 2; ks++) {
            const int k0 = ks * 16;
            uint32_t bh[4][2], bl_[4][2];
#pragma unroll
            for (int jp = 0; jp < 4; jp += 2) {
                uint32_t baddr = (uint32_t)(((wn * 32 + jp * 8 + bRowOff) * PAD2
                                            + k0 + bKOff) * 2);
                LDSM_X4(bh[jp][0], bh[jp][1], bh[jp + 1][0], bh[jp + 1][1],
                        sBh_u + baddr);
                LDSM_X4(bl_[jp][0], bl_[jp][1], bl_[jp + 1][0], bl_[jp + 1][1],
                        sBl_u + baddr);
            }
#pragma unroll
            for (int i = 0; i < 4; i++) {
                uint32_t aaddr = (uint32_t)(((wm * 64 + i * 16 + aRowOff) * PAD2
                                            + k0 + aKOff) * 2);
                uint32_t ah0, ah1, ah2, ah3, al0, al1, al2, al3;
                LDSM_X4(ah0, ah1, ah2, ah3, sAh_u + aaddr);
                LDSM_X4(al0, al1, al2, al3, sAl_u + aaddr);
#pragma unroll
                for (int j = 0; j < 4; j++)
                    MMA_BF16(acc[i][j], ah0, ah1, ah2, ah3, bh[j][0], bh[j][1]);
#pragma unroll
                for (int j = 0; j < 4; j++)
                    MMA_BF16(acc[i][j], ah0, ah1, ah2, ah3, bl_[j][0], bl_[j][1]);
#pragma unroll
                for (int j = 0; j < 4; j++)
                    MMA_BF16(acc[i][j], al0, al1, al2, al3, bh[j][0], bh[j][1]);
            }
        }
        __syncthreads();
    }

    // ---- epilogue ----
    const bool isL = (colBase < C1);
    float* X = isL ? Xl : Xr;
    const float* bs = isL ? bl1 : br1;
    const int cb = isL ? colBase : colBase - C1;
#pragma unroll
    for (int i = 0; i < 4; i++) {
        int r0 = rowBase + wm * 64 + i * 16 + lr;
#pragma unroll
        for (int j = 0; j < 4; j++) {
            int c = cb + wn * 32 + j * 8 + lc;
            float b0 = bs[c], b1 = bs[c + 1];
            if (r0 < NN) {
                float2 o = make_float2(acc[i][j][0] + b0, acc[i][j][1] + b1);
                *(float2*)(X + (size_t)r0 * C1 + c) = o;
            }
            if (r0 + 8 < NN) {
                float2 o = make_float2(acc[i][j][2] + b0, acc[i][j][3] + b1);
                *(float2*)(X + (size_t)(r0 + 8) * C1 + c) = o;
            }
        }
    }
#undef LOAD_STAGE
}

// ============================================================================
// GEMM2 via mma.sync bf16 3-product split. CTA 128(M) x 64(N), K=256 chunk 32.
// ============================================================================
#define B2_ROWS  64
#define B2_ELEM  (B2_ROWS * PAD2)     // 2560
#define B2_BYTE  (B2_ELEM * 2)        // 5120
#define STG2_BYTE (2 * T_BYTE + 2 * B2_BYTE)   // 30720
#define SMEM2_BYTES (2 * STG2_BYTE)            // 61440

__global__ __launch_bounds__(256)
void gemm2_mma(const __nv_bfloat16* __restrict__ Ah, const __nv_bfloat16* __restrict__ Al,
               const __nv_bfloat16* __restrict__ Bh, const __nv_bfloat16* __restrict__ Bl,
               const float* __restrict__ bl2, const float* __restrict__ br2,
               float* __restrict__ Xl, float* __restrict__ Xr)
{
    extern __shared__ __nv_bfloat16 sm[];
    const uint32_t smb = smem_u32(sm);

    const int tid  = threadIdx.x;
    const int wid  = tid >> 5;
    const int lane = tid & 31;
    const int wm   = wid & 1;
    const int wn   = wid >> 1;
    const int rowBase = blockIdx.x * 128;

    const int lr = lane >> 2;
    const int lc = (lane & 3) * 2;

    const int aRowOff = lane & 15;
    const int aKOff   = (lane >> 4) * 8;
    const int bGrp    = lane >> 3;
    const int bRowOff = (lane & 7) + (bGrp >> 1) * 8;
    const int bKOff   = (bGrp & 1) * 8;

#define LOAD_STAGE2(stg, kOff) do {                                           \
    uint32_t sb = smb + (stg) * STG2_BYTE;                                    \
    for (int idx = tid; idx < 512; idx += 256) {                              \
        int r  = idx >> 2;                                                    \
        int k8 = (idx & 3) * 8;                                               \
        uint32_t soff = (uint32_t)(r * (PAD2 * 2) + k8 * 2);                  \
        int ga = min(rowBase + r, NN - 1);                                    \
        CP16(sb + soff,          Ah + (size_t)ga * C1 + (kOff) + k8);         \
        CP16(sb + T_BYTE + soff, Al + (size_t)ga * C1 + (kOff) + k8);         \
    }                                                                         \
    {                                                                         \
        int r  = tid >> 2;                                                    \
        int k8 = (tid & 3) * 8;                                               \
        uint32_t soff = (uint32_t)(r * (PAD2 * 2) + k8 * 2);                  \
        CP16(sb + 2 * T_BYTE + soff,           Bh + (size_t)r * C1 + (kOff) + k8); \
        CP16(sb + 2 * T_BYTE + B2_BYTE + soff, Bl + (size_t)r * C1 + (kOff) + k8); \
    }                                                                         \
} while (0)

    float acc[4][2][4];
#pragma unroll
    for (int i = 0; i < 4; i++)
#pragma unroll
        for (int j = 0; j < 2; j++)
#pragma unroll
            for (int f = 0; f < 4; f++) acc[i][j][f] = 0.f;

    LOAD_STAGE2(0, 0);
    CP_COMMIT();

    for (int kc = 0; kc < 8; kc++) {
        const int stg = kc & 1;
        if (kc + 1 < 8) {
            LOAD_STAGE2((kc + 1) & 1, (kc + 1) * KCH);
            CP_COMMIT();
            CP_WAIT(1);
        } else {
            CP_WAIT(0);
        }
        __syncthreads();

        const uint32_t sAh_u = smb + stg * STG2_BYTE;
        const uint32_t sAl_u = sAh_u + T_BYTE;
        const uint32_t sBh_u = sAh_u + 2 * T_BYTE;
        const uint32_t sBl_u = sBh_u + B2_BYTE;

#pragma unroll
        for (int ks = 0; ks < 2; ks++) {
            const int k0 = ks * 16;
            uint32_t bh[2][2], bl_[2][2];
            {
                uint32_t baddr = (uint32_t)(((wn * 16 + bRowOff) * PAD2
                                            + k0 + bKOff) * 2);
                LDSM_X4(bh[0][0], bh[0][1], bh[1][0], bh[1][1], sBh_u + baddr);
                LDSM_X4(bl_[0][0], bl_[0][1], bl_[1][0], bl_[1][1], sBl_u + baddr);
            }
#pragma unroll
            for (int i = 0; i < 4; i++) {
                uint32_t aaddr = (uint32_t)(((wm * 64 + i * 16 + aRowOff) * PAD2
                                            + k0 + aKOff) * 2);
                uint32_t ah0, ah1, ah2, ah3, al0, al1, al2, al3;
                LDSM_X4(ah0, ah1, ah2, ah3, sAh_u + aaddr);
                LDSM_X4(al0, al1, al2, al3, sAl_u + aaddr);
#pragma unroll
                for (int j = 0; j < 2; j++)
                    MMA_BF16(acc[i][j], ah0, ah1, ah2, ah3, bh[j][0], bh[j][1]);
#pragma unroll
                for (int j = 0; j < 2; j++)
                    MMA_BF16(acc[i][j], ah0, ah1, ah2, ah3, bl_[j][0], bl_[j][1]);
#pragma unroll
                for (int j = 0; j < 2; j++)
                    MMA_BF16(acc[i][j], al0, al1, al2, al3, bh[j][0], bh[j][1]);
            }
        }
        __syncthreads();
    }

    const bool isL = (wn < 2);
    float* X = isL ? Xl : Xr;
    const float* bs = isL ? bl2 : br2;
    const int cb = isL ? wn * 16 : wn * 16 - HIDC;
#pragma unroll
    for (int i = 0; i < 4; i++) {
        int r0 = rowBase + wm * 64 + i * 16 + lr;
#pragma unroll
        for (int j = 0; j < 2; j++) {
            int c = cb + j * 8 + lc;
            float b0 = bs[c], b1 = bs[c + 1];
            if (r0 < NN) {
                float2 o = make_float2(acc[i][j][0] + b0, acc[i][j][1] + b1);
                *(float2*)(X + (size_t)r0 * HIDC + c) = o;
            }
            if (r0 + 8 < NN) {
                float2 o = make_float2(acc[i][j][2] + b0, acc[i][j][3] + b1);
                *(float2*)(X + (size_t)(r0 + 8) * HIDC + c) = o;
            }
        }
    }
#undef LOAD_STAGE2
}

// ---------------- CSR construction ------------------------------------------
__global__ void zero_deg_k(int* __restrict__ deg)
{
    int i = blockIdx.x * blockDim.x + threadIdx.x;
    if (i < NN) deg[i] = 0;
}

__global__ void hist_k(const int* __restrict__ ei, int* __restrict__ deg)
{
    int e = blockIdx.x * blockDim.x + threadIdx.x;
    if (e < EE) atomicAdd(&deg[ei[EE + e]], 1);
}

__global__ void scan1_k(const int* __restrict__ deg, int* __restrict__ rowptr,
                        int* __restrict__ bsums)
{
    __shared__ int sh[256];
    int tid = threadIdx.x;
    int i = blockIdx.x * 256 + tid;
    int v = (i < NN) ? deg[i] : 0;
    sh[tid] = v;
    __syncthreads();
#pragma unroll
    for (int off = 1; off < 256; off <<= 1) {
        int t = (tid >= off) ? sh[tid - off] : 0;
        __syncthreads();
        sh[tid] += t;
        __syncthreads();
    }
    if (i < NN) rowptr[i] = sh[tid] - v;
    if (tid == 255) bsums[blockIdx.x] = sh[255];
}

__global__ void scan2_k(int* __restrict__ bsums, int nb)
{
    __shared__ int sh[256];
    int tid = threadIdx.x;
    int v = (tid < nb) ? bsums[tid] : 0;
    sh[tid] = v;
    __syncthreads();
#pragma unroll
    for (int off = 1; off < 256; off <<= 1) {
        int t = (tid >= off) ? sh[tid - off] : 0;
        __syncthreads();
        sh[tid] += t;
        __syncthreads();
    }
    if (tid < nb) bsums[tid] = sh[tid] - v;
}

__global__ void scan3_k(int* __restrict__ rowptr, const int* __restrict__ bsums,
                        int* __restrict__ cursor)
{
    int i = blockIdx.x * blockDim.x + threadIdx.x;
    if (i >= NN) return;
    int r = rowptr[i] + bsums[i >> 8];
    rowptr[i] = r;
    cursor[i] = r;
}

__global__ void scatter_k(const int* __restrict__ ei, int* __restrict__ cursor,
                          int* __restrict__ csrc)
{
    int e = blockIdx.x * blockDim.x + threadIdx.x;
    if (e >= EE) return;
    int d = ei[EE + e];
    int pos = atomicAdd(&cursor[d], 1);
    csrc[pos] = ei[e];
}

// ---------------- fused GATv2 edge phase, layer 1 ---------------------------
// paired-edge processing: two independent row loads + two interleaved shfl
// chains per iteration; clamped-index prefetch one pair ahead.
__global__ __launch_bounds__(256)
void edge_fused1_k(const int* __restrict__ rowptr, const int* __restrict__ deg,
                   const int* __restrict__ csrc,
                   const float* __restrict__ xl, const float* __restrict__ xr,
                   const float* __restrict__ att, const float* __restrict__ bias,
                   __nv_bfloat16* __restrict__ h1h, __nv_bfloat16* __restrict__ h1l)
{
    int w = (blockIdx.x * blockDim.x + threadIdx.x) >> 5;
    if (w >= NN) return;
    int lane = threadIdx.x & 31;

    const float4* pb = reinterpret_cast<const float4*>(xr + (size_t)w * C1 + lane * 8);
    float4 b0 = pb[0], b1 = pb[1];
    const float4* pt = reinterpret_cast<const float4*>(att + lane * 8);
    float4 t0 = pt[0], t1 = pt[1];

    float acc[8] = {};
    float den = 0.f;

    int start = rowptr[w];
    int dg    = deg[w];

    float4 a0, a1, c0, c1;
    if (dg > 0) {
        int s0 = csrc[start];
        int s1 = csrc[start + min(1, dg - 1)];
        const float4* p0 = reinterpret_cast<const float4*>(xl + (size_t)s0 * C1 + lane * 8);
        const float4* p1 = reinterpret_cast<const float4*>(xl + (size_t)s1 * C1 + lane * 8);
        a0 = p0[0]; a1 = p0[1];
        c0 = p1[0]; c1 = p1[1];
    }

    int i = 0;
    for (; i + 2 <= dg; i += 2) {
        // clamped prefetch of the next pair (duplicates dg-1 harmlessly at tail)
        int sn0 = csrc[start + min(i + 2, dg - 1)];
        int sn1 = csrc[start + min(i + 3, dg - 1)];
        const float4* pn0 = reinterpret_cast<const float4*>(xl + (size_t)sn0 * C1 + lane * 8);
        const float4* pn1 = reinterpret_cast<const float4*>(xl + (size_t)sn1 * C1 + lane * 8);
        float4 n0 = pn0[0], n1 = pn0[1];
        float4 m0 = pn1[0], m1 = pn1[1];

        float p = lrelu(a0.x + b0.x) * t0.x + lrelu(a0.y + b0.y) * t0.y
                + lrelu(a0.z + b0.z) * t0.z + lrelu(a0.w + b0.w) * t0.w
                + lrelu(a1.x + b1.x) * t1.x + lrelu(a1.y + b1.y) * t1.y
                + lrelu(a1.z + b1.z) * t1.z + lrelu(a1.w + b1.w) * t1.w;
        float q = lrelu(c0.x + b0.x) * t0.x + lrelu(c0.y + b0.y) * t0.y
                + lrelu(c0.z + b0.z) * t0.z + lrelu(c0.w + b0.w) * t0.w
                + lrelu(c1.x + b1.x) * t1.x + lrelu(c1.y + b1.y) * t1.y
                + lrelu(c1.z + b1.z) * t1.z + lrelu(c1.w + b1.w) * t1.w;
        p += __shfl_xor_sync(0xffffffffu, p, 1);
        q += __shfl_xor_sync(0xffffffffu, q, 1);
        p += __shfl_xor_sync(0xffffffffu, p, 2);
        q += __shfl_xor_sync(0xffffffffu, q, 2);
        float e0 = __expf(p);
        float e1 = __expf(q);
        den += e0 + e1;
        acc[0] += e0 * a0.x + e1 * c0.x; acc[1] += e0 * a0.y + e1 * c0.y;
        acc[2] += e0 * a0.z + e1 * c0.z; acc[3] += e0 * a0.w + e1 * c0.w;
        acc[4] += e0 * a1.x + e1 * c1.x; acc[5] += e0 * a1.y + e1 * c1.y;
        acc[6] += e0 * a1.z + e1 * c1.z; acc[7] += e0 * a1.w + e1 * c1.w;

        a0 = n0; a1 = n1; c0 = m0; c1 = m1;
    }
    if (i < dg) {     // odd tail: a0/a1 hold row for edge dg-1 (clamped prefetch)
        float p = lrelu(a0.x + b0.x) * t0.x + lrelu(a0.y + b0.y) * t0.y
                + lrelu(a0.z + b0.z) * t0.z + lrelu(a0.w + b0.w) * t0.w
                + lrelu(a1.x + b1.x) * t1.x + lrelu(a1.y + b1.y) * t1.y
                + lrelu(a1.z + b1.z) * t1.z + lrelu(a1.w + b1.w) * t1.w;
        p += __shfl_xor_sync(0xffffffffu, p, 1);
        p += __shfl_xor_sync(0xffffffffu, p, 2);
        float e0 = __expf(p);
        den += e0;
        acc[0] += e0 * a0.x; acc[1] += e0 * a0.y;
        acc[2] += e0 * a0.z; acc[3] += e0 * a0.w;
        acc[4] += e0 * a1.x; acc[5] += e0 * a1.y;
        acc[6] += e0 * a1.z; acc[7] += e0 * a1.w;
    }

    float inv = 1.f / (den + 1e-16f);
    const float* bi = bias + lane * 8;
    __nv_bfloat16 hh[8], ll[8];
#pragma unroll
    for (int j = 0; j < 8; j++) {
        float v = elu(acc[j] * inv + bi[j]);
        __nv_bfloat16 h = __float2bfloat16(v);
        hh[j] = h;
        ll[j] = __float2bfloat16(v - __bfloat162float(h));
    }
    *(uint4*)(h1h + (size_t)w * C1 + lane * 8) = *(const uint4*)hh;
    *(uint4*)(h1l + (size_t)w * C1 + lane * 8) = *(const uint4*)ll;
}

// ---------------- fused edge phase layer 2 + final linear head --------------
// paired-edge processing: two interleaved 5-shfl reduce chains per iteration.
__global__ __launch_bounds__(256)
void edge_fused2_head_k(const int* __restrict__ rowptr, const int* __restrict__ deg,
                        const int* __restrict__ csrc,
                        const float* __restrict__ xl, const float* __restrict__ xr,
                        const float* __restrict__ att, const float* __restrict__ bias,
                        const float* __restrict__ Wlin, const float* __restrict__ blin,
                        float* __restrict__ out)
{
    __shared__ float Ws[HIDC][OUTDIM];      // 32x64 = 8 KB
    __shared__ float bs[OUTDIM];

    for (int i = threadIdx.x; i < HIDC * OUTDIM; i += blockDim.x)
        Ws[i >> 6][i & 63] = Wlin[i];
    if (threadIdx.x < OUTDIM) bs[threadIdx.x] = blin[threadIdx.x];
    __syncthreads();

    int w = (blockIdx.x * blockDim.x + threadIdx.x) >> 5;
    int lane = threadIdx.x & 31;
    if (w >= NN) return;

    float b = xr[(size_t)w * HIDC + lane];
    float t = att[lane];

    float acc = 0.f, den = 0.f;
    int start = rowptr[w];
    int dg    = deg[w];

    float a0f = 0.f, a1f = 0.f;
    if (dg > 0) {
        int s0 = csrc[start];
        int s1 = csrc[start + min(1, dg - 1)];
        a0f = xl[(size_t)s0 * HIDC + lane];
        a1f = xl[(size_t)s1 * HIDC + lane];
    }

    int i = 0;
    for (; i + 2 <= dg; i += 2) {
        int sn0 = csrc[start + min(i + 2, dg - 1)];
        int sn1 = csrc[start + min(i + 3, dg - 1)];
        float n0 = xl[(size_t)sn0 * HIDC + lane];
        float n1 = xl[(size_t)sn1 * HIDC + lane];

        float p = lrelu(a0f + b) * t;
        float q = lrelu(a1f + b) * t;
        p += __shfl_xor_sync(0xffffffffu, p, 16);
        q += __shfl_xor_sync(0xffffffffu, q, 16);
        p += __shfl_xor_sync(0xffffffffu, p, 8);
        q += __shfl_xor_sync(0xffffffffu, q, 8);
        p += __shfl_xor_sync(0xffffffffu, p, 4);
        q += __shfl_xor_sync(0xffffffffu, q, 4);
        p += __shfl_xor_sync(0xffffffffu, p, 2);
        q += __shfl_xor_sync(0xffffffffu, q, 2);
        p += __shfl_xor_sync(0xffffffffu, p, 1);
        q += __shfl_xor_sync(0xffffffffu, q, 1);
        float e0 = __expf(p);
        float e1 = __expf(q);
        den += e0 + e1;
        acc += e0 * a0f + e1 * a1f;

        a0f = n0; a1f = n1;
    }
    if (i < dg) {      // odd tail: a0f holds row for edge dg-1
        float p = lrelu(a0f + b) * t;
        p += __shfl_xor_sync(0xffffffffu, p, 16);
        p += __shfl_xor_sync(0xffffffffu, p, 8);
        p += __shfl_xor_sync(0xffffffffu, p, 4);
        p += __shfl_xor_sync(0xffffffffu, p, 2);
        p += __shfl_xor_sync(0xffffffffu, p, 1);
        float e0 = __expf(p);
        den += e0;
        acc += e0 * a0f;
    }

    float inv = 1.f / (den + 1e-16f);
    float hval = elu(acc * inv + bias[lane]);   // h2[w][lane]

    float o0 = bs[lane];
    float o1 = bs[lane + 32];
#pragma unroll
    for (int k = 0; k < HIDC; k++) {
        float v = __shfl_sync(0xffffffffu, hval, k);
        o0 = fmaf(v, Ws[k][lane],      o0);
        o1 = fmaf(v, Ws[k][lane + 32], o1);
    }
    out[(size_t)w * OUTDIM + lane]      = o0;
    out[(size_t)w * OUTDIM + lane + 32] = o1;
}

// ---------------- launch ------------------------------------------------------
extern "C" void kernel_launch(void* const* d_in, const int* in_sizes, int n_in,
                              void* d_out, int out_size)
{
    const float* x     = (const float*)d_in[0];
    const int*   ei    = (const int*)d_in[1];
    const float* W1l   = (const float*)d_in[2];
    const float* b1l   = (const float*)d_in[3];
    const float* W1r   = (const float*)d_in[4];
    const float* b1r   = (const float*)d_in[5];
    const float* att1  = (const float*)d_in[6];
    const float* bias1 = (const float*)d_in[7];
    const float* W2l   = (const float*)d_in[8];
    const float* b2l   = (const float*)d_in[9];
    const float* W2r   = (const float*)d_in[10];
    const float* b2r   = (const float*)d_in[11];
    const float* att2  = (const float*)d_in[12];
    const float* bias2 = (const float*)d_in[13];
    const float* Wlin  = (const float*)d_in[14];
    const float* blin  = (const float*)d_in[15];
    float* out = (float*)d_out;

    float *xl1, *xr1, *xl2, *xr2;
    int *deg, *rowptr, *cursor, *csrc, *bsums;
    __nv_bfloat16 *Ah, *Al, *Bh, *Bl, *H1h, *H1l, *B2h, *B2l;
    cudaGetSymbolAddress((void**)&xl1, g_xl1);
    cudaGetSymbolAddress((void**)&xr1, g_xr1);
    cudaGetSymbolAddress((void**)&xl2, g_xl2);
    cudaGetSymbolAddress((void**)&xr2, g_xr2);
    cudaGetSymbolAddress((void**)&deg,    g_deg);
    cudaGetSymbolAddress((void**)&rowptr, g_rowptr);
    cudaGetSymbolAddress((void**)&cursor, g_cursor);
    cudaGetSymbolAddress((void**)&csrc,   g_csrc);
    cudaGetSymbolAddress((void**)&bsums,  g_bsums);
    cudaGetSymbolAddress((void**)&Ah,  g_Ah);
    cudaGetSymbolAddress((void**)&Al,  g_Al);
    cudaGetSymbolAddress((void**)&Bh,  g_Bh);
    cudaGetSymbolAddress((void**)&Bl,  g_Bl);
    cudaGetSymbolAddress((void**)&H1h, g_H1h);
    cudaGetSymbolAddress((void**)&H1l, g_H1l);
    cudaGetSymbolAddress((void**)&B2h, g_B2h);
    cudaGetSymbolAddress((void**)&B2l, g_B2l);

    cudaFuncSetAttribute(gemm1_mma, cudaFuncAttributeMaxDynamicSharedMemorySize,
                         SMEM_BYTES);
    cudaFuncSetAttribute(gemm2_mma, cudaFuncAttributeMaxDynamicSharedMemorySize,
                         SMEM2_BYTES);

    const int TPB = 256;
    const int nScanBlocks = (NN + 255) / 256;       // 196

    // ---- stream fork: CSR build runs concurrently with conv + GEMM1 ----
    cudaStream_t s2;
    cudaStreamCreateWithFlags(&s2, cudaStreamNonBlocking);
    cudaEvent_t e1, e2;
    cudaEventCreateWithFlags(&e1, cudaEventDisableTiming);
    cudaEventCreateWithFlags(&e2, cudaEventDisableTiming);

    cudaEventRecord(e1, 0);
    cudaStreamWaitEvent(s2, e1, 0);

    // side stream: CSR pipeline + W2 conversion (independent of GEMM1 chain)
    zero_deg_k<<<(NN + TPB - 1) / TPB, TPB, 0, s2>>>(deg);
    hist_k<<<(EE + TPB - 1) / TPB, TPB, 0, s2>>>(ei, deg);
    scan1_k<<<nScanBlocks, 256, 0, s2>>>(deg, rowptr, bsums);
    scan2_k<<<1, 256, 0, s2>>>(bsums, nScanBlocks);
    scan3_k<<<(NN + TPB - 1) / TPB, TPB, 0, s2>>>(rowptr, bsums, cursor);
    scatter_k<<<(EE + TPB - 1) / TPB, TPB, 0, s2>>>(ei, cursor, csrc);
    conv_w2_k<<<(NB2 * C1 + TPB - 1) / TPB, TPB, 0, s2>>>(W2l, W2r, B2h, B2l);
    cudaEventRecord(e2, s2);

    // main stream: conversions + GEMM1
    conv_x_k<<<(NN * INDIM + TPB - 1) / TPB, TPB>>>(x, Ah, Al);
    conv_w_k<<<(NB * INDIM + TPB - 1) / TPB, TPB>>>(W1l, W1r, Bh, Bl);

    dim3 gg1(4, (NN + 127) / 128);
    gemm1_mma<<<gg1, TPB, SMEM_BYTES>>>(Ah, Al, Bh, Bl, b1l, b1r, xl1, xr1);

    // join: edge phase needs both GEMM1 outputs and CSR
    cudaStreamWaitEvent(0, e2, 0);

    int eblocks = (NN * 32 + TPB - 1) / TPB;
    edge_fused1_k<<<eblocks, TPB>>>(rowptr, deg, csrc, xl1, xr1,
                                    att1, bias1, H1h, H1l);

    gemm2_mma<<<(NN + 127) / 128, TPB, SMEM2_BYTES>>>(H1h, H1l, B2h, B2l,
                                                      b2l, b2r, xl2, xr2);

    edge_fused2_head_k<<<eblocks, TPB>>>(rowptr, deg, csrc, xl2, xr2,
                                         att2, bias2, Wlin, blin, out);
}

// round 14
// speedup vs baseline: 1.1344x; 1.1344x over previous
#include <cuda_runtime.h>
#include <cuda_fp16.h>
#include <cstdint>

#define NN      50000
#define EE      800000
#define INDIM   256
#define HIDC    32
#define NHEADS  8
#define OUTDIM  64
#define C1      (NHEADS * HIDC)   // 256
#define NB      512               // total output cols of GEMM1 (Wl|Wr)
#define NB2     64                // total output cols of GEMM2 (W2l|W2r)
#define NEGSLOPE 0.2f

typedef unsigned long long u64;

// ---------------- scratch (device globals) ---------------------------------
__device__ float g_xl1[(size_t)NN * C1];
__device__ float g_xr1[(size_t)NN * C1];
__device__ float g_xl2[(size_t)NN * HIDC];
__device__ float g_xr2[(size_t)NN * HIDC];
__device__ int   g_deg   [NN];
__device__ int   g_rowptr[NN];
__device__ int   g_cursor[NN];
__device__ int   g_csrc  [EE];
__device__ int   g_bsums [256];
// fp16 operands (2-product split: A single fp16, B split hi/lo)
__device__ __align__(16) __half g_Ah [(size_t)NN * INDIM];
__device__ __align__(16) __half g_Bh [(size_t)NB * INDIM];
__device__ __align__(16) __half g_Bl [(size_t)NB * INDIM];
__device__ __align__(16) __half g_H1 [(size_t)NN * C1];
__device__ __align__(16) __half g_B2h[(size_t)NB2 * C1];
__device__ __align__(16) __half g_B2l[(size_t)NB2 * C1];

// ---------------- helpers ---------------------------------------------------
__device__ __forceinline__ float lrelu(float v) { return v > 0.f ? v : NEGSLOPE * v; }
__device__ __forceinline__ float elu(float v)   { return v > 0.f ? v : expm1f(v); }

__device__ __forceinline__ uint32_t smem_u32(const void* p)
{
    uint32_t a;
    asm("{ .reg .u64 t; cvta.to.shared.u64 t, %1; cvt.u32.u64 %0, t; }"
        : "=r"(a) : "l"(p));
    return a;
}

// fp16 tensor-core mma (sm_80+ base)
#define MMA_F16(d, a0, a1, a2, a3, b0, b1)                                   \
    asm volatile(                                                            \
        "mma.sync.aligned.m16n8k16.row.col.f32.f16.f16.f32 "                 \
        "{%0,%1,%2,%3}, {%4,%5,%6,%7}, {%8,%9}, {%0,%1,%2,%3};"              \
        : "+f"((d)[0]), "+f"((d)[1]), "+f"((d)[2]), "+f"((d)[3])             \
        : "r"(a0), "r"(a1), "r"(a2), "r"(a3), "r"(b0), "r"(b1))

// ldmatrix (sm_75+ base)
#define LDSM_X4(r0, r1, r2, r3, addr)                                        \
    asm volatile("ldmatrix.sync.aligned.m8n8.x4.shared.b16 {%0,%1,%2,%3}, [%4];" \
                 : "=r"(r0), "=r"(r1), "=r"(r2), "=r"(r3) : "r"(addr))

// cp.async (sm_80+ base)
#define CP16(dst_u32, src_ptr) \
    asm volatile("cp.async.cg.shared.global [%0], [%1], 16;" \
                 :: "r"(dst_u32), "l"(src_ptr))
#define CP_COMMIT() asm volatile("cp.async.commit_group;" ::: "memory")
#define CP_WAIT(n)  asm volatile("cp.async.wait_group %0;" :: "n"(n) : "memory")

// ---------------- conversion kernels -----------------------------------------
__global__ void conv_x_k(const float* __restrict__ x, __half* __restrict__ Ah)
{
    size_t i = (size_t)blockIdx.x * blockDim.x + threadIdx.x;
    if (i >= (size_t)NN * INDIM) return;
    Ah[i] = __float2half(x[i]);
}

__global__ void conv_w_k(const float* __restrict__ W1l, const float* __restrict__ W1r,
                         __half* __restrict__ Bh, __half* __restrict__ Bl)
{
    int i = blockIdx.x * blockDim.x + threadIdx.x;
    if (i >= NB * INDIM) return;
    int n = i >> 8;
    int k = i & 255;
    float v = (n < C1) ? W1l[(size_t)k * C1 + n] : W1r[(size_t)k * C1 + (n - C1)];
    __half h = __float2half(v);
    Bh[i] = h;
    Bl[i] = __float2half(v - __half2float(h));
}

__global__ void conv_w2_k(const float* __restrict__ W2l, const float* __restrict__ W2r,
                          __half* __restrict__ B2h, __half* __restrict__ B2l)
{
    int i = blockIdx.x * blockDim.x + threadIdx.x;
    if (i >= NB2 * C1) return;
    int n = i >> 8;          // 0..63
    int k = i & 255;
    float v = (n < HIDC) ? W2l[(size_t)k * HIDC + n]
                         : W2r[(size_t)k * HIDC + (n - HIDC)];
    __half h = __float2half(v);
    B2h[i] = h;
    B2l[i] = __float2half(v - __half2float(h));
}

// ============================================================================
// GEMM1 via mma.sync fp16 2-product split (A fp16, B = Bh+Bl),
// cp.async double-buffered, ldmatrix. CTA 128x128, K chunk 32, 8 warps 2x4.
// Stage = Ah + Bh + Bl tiles (3 x 10240 B); 2 stages = 61440 B -> 3 CTAs/SM.
// ============================================================================
#define KCH    32
#define PAD2   40
#define T_ELEM (128 * PAD2)
#define T_BYTE (T_ELEM * 2)          // 10240
#define STG_BYTE (3 * T_BYTE)        // 30720
#define SMEM_BYTES (2 * STG_BYTE)    // 61440

__global__ __launch_bounds__(256)
void gemm1_mma(const __half* __restrict__ Ah,
               const __half* __restrict__ Bh, const __half* __restrict__ Bl,
               const float* __restrict__ bl1, const float* __restrict__ br1,
               float* __restrict__ Xl, float* __restrict__ Xr)
{
    extern __shared__ __half sm[];
    const uint32_t smb = smem_u32(sm);

    const int tid  = threadIdx.x;
    const int wid  = tid >> 5;
    const int lane = tid & 31;
    const int wm   = wid & 1;
    const int wn   = wid >> 1;
    const int rowBase = blockIdx.y * 128;
    const int colBase = blockIdx.x * 128;

    const int lr = lane >> 2;
    const int lc = (lane & 3) * 2;

    const int aRowOff = lane & 15;
    const int aKOff   = (lane >> 4) * 8;
    const int bGrp    = lane >> 3;
    const int bRowOff = (lane & 7) + (bGrp >> 1) * 8;
    const int bKOff   = (bGrp & 1) * 8;

#define LOAD_STAGE(stg, kOff) do {                                            \
    uint32_t sb = smb + (stg) * STG_BYTE;                                     \
    for (int idx = tid; idx < 512; idx += 256) {                              \
        int r  = idx >> 2;                                                    \
        int k8 = (idx & 3) * 8;                                               \
        uint32_t soff = (uint32_t)(r * (PAD2 * 2) + k8 * 2);                  \
        int ga = min(rowBase + r, NN - 1);                                    \
        int gb = colBase + r;                                                 \
        CP16(sb + soff,              Ah + (size_t)ga * INDIM + (kOff) + k8);  \
        CP16(sb + T_BYTE + soff,     Bh + (size_t)gb * INDIM + (kOff) + k8);  \
        CP16(sb + 2 * T_BYTE + soff, Bl + (size_t)gb * INDIM + (kOff) + k8);  \
    }                                                                         \
} while (0)

    float acc[4][4][4];
#pragma unroll
    for (int i = 0; i < 4; i++)
#pragma unroll
        for (int j = 0; j < 4; j++)
#pragma unroll
            for (int f = 0; f < 4; f++) acc[i][j][f] = 0.f;

    LOAD_STAGE(0, 0);
    CP_COMMIT();

    for (int kc = 0; kc < 8; kc++) {
        const int stg = kc & 1;
        if (kc + 1 < 8) {
            LOAD_STAGE((kc + 1) & 1, (kc + 1) * KCH);
            CP_COMMIT();
            CP_WAIT(1);
        } else {
            CP_WAIT(0);
        }
        __syncthreads();

        const uint32_t sA_u  = smb + stg * STG_BYTE;
        const uint32_t sBh_u = sA_u + T_BYTE;
        const uint32_t sBl_u = sA_u + 2 * T_BYTE;

#pragma unroll
        for (int ks = 0; ks < 2; ks++) {
            const int k0 = ks * 16;
            uint32_t bh[4][2], bl_[4][2];
#pragma unroll
            for (int jp = 0; jp < 4; jp += 2) {
                uint32_t baddr = (uint32_t)(((wn * 32 + jp * 8 + bRowOff) * PAD2
                                            + k0 + bKOff) * 2);
                LDSM_X4(bh[jp][0], bh[jp][1], bh[jp + 1][0], bh[jp + 1][1],
                        sBh_u + baddr);
                LDSM_X4(bl_[jp][0], bl_[jp][1], bl_[jp + 1][0], bl_[jp + 1][1],
                        sBl_u + baddr);
            }
#pragma unroll
            for (int i = 0; i < 4; i++) {
                uint32_t aaddr = (uint32_t)(((wm * 64 + i * 16 + aRowOff) * PAD2
                                            + k0 + aKOff) * 2);
                uint32_t a0, a1, a2, a3;
                LDSM_X4(a0, a1, a2, a3, sA_u + aaddr);
#pragma unroll
                for (int j = 0; j < 4; j++)
                    MMA_F16(acc[i][j], a0, a1, a2, a3, bh[j][0], bh[j][1]);
#pragma unroll
                for (int j = 0; j < 4; j++)
                    MMA_F16(acc[i][j], a0, a1, a2, a3, bl_[j][0], bl_[j][1]);
            }
        }
        __syncthreads();
    }

    // ---- epilogue ----
    const bool isL = (colBase < C1);
    float* X = isL ? Xl : Xr;
    const float* bs = isL ? bl1 : br1;
    const int cb = isL ? colBase : colBase - C1;
#pragma unroll
    for (int i = 0; i < 4; i++) {
        int r0 = rowBase + wm * 64 + i * 16 + lr;
#pragma unroll
        for (int j = 0; j < 4; j++) {
            int c = cb + wn * 32 + j * 8 + lc;
            float b0 = bs[c], b1 = bs[c + 1];
            if (r0 < NN) {
                float2 o = make_float2(acc[i][j][0] + b0, acc[i][j][1] + b1);
                *(float2*)(X + (size_t)r0 * C1 + c) = o;
            }
            if (r0 + 8 < NN) {
                float2 o = make_float2(acc[i][j][2] + b0, acc[i][j][3] + b1);
                *(float2*)(X + (size_t)(r0 + 8) * C1 + c) = o;
            }
        }
    }
#undef LOAD_STAGE
}

// ============================================================================
// GEMM2 via mma.sync fp16 2-product split. CTA 128x64, K=256 chunk 32.
// Stage = H1 tile (10240) + B2h + B2l (2 x 5120) = 20480; 2 stages = 40960.
// ============================================================================
#define B2_ROWS  64
#define B2_ELEM  (B2_ROWS * PAD2)     // 2560
#define B2_BYTE  (B2_ELEM * 2)        // 5120
#define STG2_BYTE (T_BYTE + 2 * B2_BYTE)       // 20480
#define SMEM2_BYTES (2 * STG2_BYTE)            // 40960

__global__ __launch_bounds__(256)
void gemm2_mma(const __half* __restrict__ Ah,
               const __half* __restrict__ Bh, const __half* __restrict__ Bl,
               const float* __restrict__ bl2, const float* __restrict__ br2,
               float* __restrict__ Xl, float* __restrict__ Xr)
{
    extern __shared__ __half sm[];
    const uint32_t smb = smem_u32(sm);

    const int tid  = threadIdx.x;
    const int wid  = tid >> 5;
    const int lane = tid & 31;
    const int wm   = wid & 1;
    const int wn   = wid >> 1;       // 0..3 -> 16-col slice
    const int rowBase = blockIdx.x * 128;

    const int lr = lane >> 2;
    const int lc = (lane & 3) * 2;

    const int aRowOff = lane & 15;
    const int aKOff   = (lane >> 4) * 8;
    const int bGrp    = lane >> 3;
    const int bRowOff = (lane & 7) + (bGrp >> 1) * 8;
    const int bKOff   = (bGrp & 1) * 8;

#define LOAD_STAGE2(stg, kOff) do {                                           \
    uint32_t sb = smb + (stg) * STG2_BYTE;                                    \
    for (int idx = tid; idx < 512; idx += 256) {                              \
        int r  = idx >> 2;                                                    \
        int k8 = (idx & 3) * 8;                                               \
        uint32_t soff = (uint32_t)(r * (PAD2 * 2) + k8 * 2);                  \
        int ga = min(rowBase + r, NN - 1);                                    \
        CP16(sb + soff, Ah + (size_t)ga * C1 + (kOff) + k8);                  \
    }                                                                         \
    {                                                                         \
        int r  = tid >> 2;       /* 0..63 */                                  \
        int k8 = (tid & 3) * 8;                                               \
        uint32_t soff = (uint32_t)(r * (PAD2 * 2) + k8 * 2);                  \
        CP16(sb + T_BYTE + soff,           Bh + (size_t)r * C1 + (kOff) + k8);\
        CP16(sb + T_BYTE + B2_BYTE + soff, Bl + (size_t)r * C1 + (kOff) + k8);\
    }                                                                         \
} while (0)

    float acc[4][2][4];
#pragma unroll
    for (int i = 0; i < 4; i++)
#pragma unroll
        for (int j = 0; j < 2; j++)
#pragma unroll
            for (int f = 0; f < 4; f++) acc[i][j][f] = 0.f;

    LOAD_STAGE2(0, 0);
    CP_COMMIT();

    for (int kc = 0; kc < 8; kc++) {
        const int stg = kc & 1;
        if (kc + 1 < 8) {
            LOAD_STAGE2((kc + 1) & 1, (kc + 1) * KCH);
            CP_COMMIT();
            CP_WAIT(1);
        } else {
            CP_WAIT(0);
        }
        __syncthreads();

        const uint32_t sA_u  = smb + stg * STG2_BYTE;
        const uint32_t sBh_u = sA_u + T_BYTE;
        const uint32_t sBl_u = sBh_u + B2_BYTE;

#pragma unroll
        for (int ks = 0; ks < 2; ks++) {
            const int k0 = ks * 16;
            uint32_t bh[2][2], bl_[2][2];
            {
                uint32_t baddr = (uint32_t)(((wn * 16 + bRowOff) * PAD2
                                            + k0 + bKOff) * 2);
                LDSM_X4(bh[0][0], bh[0][1], bh[1][0], bh[1][1], sBh_u + baddr);
                LDSM_X4(bl_[0][0], bl_[0][1], bl_[1][0], bl_[1][1], sBl_u + baddr);
            }
#pragma unroll
            for (int i = 0; i < 4; i++) {
                uint32_t aaddr = (uint32_t)(((wm * 64 + i * 16 + aRowOff) * PAD2
                                            + k0 + aKOff) * 2);
                uint32_t a0, a1, a2, a3;
                LDSM_X4(a0, a1, a2, a3, sA_u + aaddr);
#pragma unroll
                for (int j = 0; j < 2; j++)
                    MMA_F16(acc[i][j], a0, a1, a2, a3, bh[j][0], bh[j][1]);
#pragma unroll
                for (int j = 0; j < 2; j++)
                    MMA_F16(acc[i][j], a0, a1, a2, a3, bl_[j][0], bl_[j][1]);
            }
        }
        __syncthreads();
    }

    const bool isL = (wn < 2);
    float* X = isL ? Xl : Xr;
    const float* bs = isL ? bl2 : br2;
    const int cb = isL ? wn * 16 : wn * 16 - HIDC;
#pragma unroll
    for (int i = 0; i < 4; i++) {
        int r0 = rowBase + wm * 64 + i * 16 + lr;
#pragma unroll
        for (int j = 0; j < 2; j++) {
            int c = cb + j * 8 + lc;
            float b0 = bs[c], b1 = bs[c + 1];
            if (r0 < NN) {
                float2 o = make_float2(acc[i][j][0] + b0, acc[i][j][1] + b1);
                *(float2*)(X + (size_t)r0 * HIDC + c) = o;
            }
            if (r0 + 8 < NN) {
                float2 o = make_float2(acc[i][j][2] + b0, acc[i][j][3] + b1);
                *(float2*)(X + (size_t)(r0 + 8) * HIDC + c) = o;
            }
        }
    }
#undef LOAD_STAGE2
}

// ---------------- CSR construction ------------------------------------------
__global__ void zero_deg_k(int* __restrict__ deg)
{
    int i = blockIdx.x * blockDim.x + threadIdx.x;
    if (i < NN) deg[i] = 0;
}

__global__ void hist_k(const int* __restrict__ ei, int* __restrict__ deg)
{
    int e = blockIdx.x * blockDim.x + threadIdx.x;
    if (e < EE) atomicAdd(&deg[ei[EE + e]], 1);
}

__global__ void scan1_k(const int* __restrict__ deg, int* __restrict__ rowptr,
                        int* __restrict__ bsums)
{
    __shared__ int sh[256];
    int tid = threadIdx.x;
    int i = blockIdx.x * 256 + tid;
    int v = (i < NN) ? deg[i] : 0;
    sh[tid] = v;
    __syncthreads();
#pragma unroll
    for (int off = 1; off < 256; off <<= 1) {
        int t = (tid >= off) ? sh[tid - off] : 0;
        __syncthreads();
        sh[tid] += t;
        __syncthreads();
    }
    if (i < NN) rowptr[i] = sh[tid] - v;
    if (tid == 255) bsums[blockIdx.x] = sh[255];
}

__global__ void scan2_k(int* __restrict__ bsums, int nb)
{
    __shared__ int sh[256];
    int tid = threadIdx.x;
    int v = (tid < nb) ? bsums[tid] : 0;
    sh[tid] = v;
    __syncthreads();
#pragma unroll
    for (int off = 1; off < 256; off <<= 1) {
        int t = (tid >= off) ? sh[tid - off] : 0;
        __syncthreads();
        sh[tid] += t;
        __syncthreads();
    }
    if (tid < nb) bsums[tid] = sh[tid] - v;
}

__global__ void scan3_k(int* __restrict__ rowptr, const int* __restrict__ bsums,
                        int* __restrict__ cursor)
{
    int i = blockIdx.x * blockDim.x + threadIdx.x;
    if (i >= NN) return;
    int r = rowptr[i] + bsums[i >> 8];
    rowptr[i] = r;
    cursor[i] = r;
}

__global__ void scatter_k(const int* __restrict__ ei, int* __restrict__ cursor,
                          int* __restrict__ csrc)
{
    int e = blockIdx.x * blockDim.x + threadIdx.x;
    if (e >= EE) return;
    int d = ei[EE + e];
    int pos = atomicAdd(&cursor[d], 1);
    csrc[pos] = ei[e];
}

// ---------------- fused GATv2 edge phase, layer 1 ---------------------------
// outputs h1 directly as fp16 (consumed by gemm2_mma)
__global__ __launch_bounds__(256)
void edge_fused1_k(const int* __restrict__ rowptr, const int* __restrict__ deg,
                   const int* __restrict__ csrc,
                   const float* __restrict__ xl, const float* __restrict__ xr,
                   const float* __restrict__ att, const float* __restrict__ bias,
                   __half* __restrict__ h1)
{
    int w = (blockIdx.x * blockDim.x + threadIdx.x) >> 5;
    if (w >= NN) return;
    int lane = threadIdx.x & 31;

    const float4* pb = reinterpret_cast<const float4*>(xr + (size_t)w * C1 + lane * 8);
    float4 b0 = pb[0], b1 = pb[1];
    const float4* pt = reinterpret_cast<const float4*>(att + lane * 8);
    float4 t0 = pt[0], t1 = pt[1];

    float acc[8] = {};
    float den = 0.f;

    int start = rowptr[w];
    int dg    = deg[w];

    int s = (dg > 0) ? csrc[start] : 0;
    const float4* pa = reinterpret_cast<const float4*>(xl + (size_t)s * C1 + lane * 8);
    float4 a0 = pa[0], a1 = pa[1];

    for (int i = 0; i < dg; i++) {
        int snext = (i + 1 < dg) ? csrc[start + i + 1] : s;
        const float4* pn = reinterpret_cast<const float4*>(
            xl + (size_t)snext * C1 + lane * 8);
        float4 n0 = pn[0], n1 = pn[1];

        float p = lrelu(a0.x + b0.x) * t0.x + lrelu(a0.y + b0.y) * t0.y
                + lrelu(a0.z + b0.z) * t0.z + lrelu(a0.w + b0.w) * t0.w
                + lrelu(a1.x + b1.x) * t1.x + lrelu(a1.y + b1.y) * t1.y
                + lrelu(a1.z + b1.z) * t1.z + lrelu(a1.w + b1.w) * t1.w;
        p += __shfl_xor_sync(0xffffffffu, p, 1);
        p += __shfl_xor_sync(0xffffffffu, p, 2);
        float ex = __expf(p);
        den += ex;
        acc[0] += ex * a0.x; acc[1] += ex * a0.y;
        acc[2] += ex * a0.z; acc[3] += ex * a0.w;
        acc[4] += ex * a1.x; acc[5] += ex * a1.y;
        acc[6] += ex * a1.z; acc[7] += ex * a1.w;

        a0 = n0; a1 = n1;
    }

    float inv = 1.f / (den + 1e-16f);
    const float* bi = bias + lane * 8;
    __half hh[8];
#pragma unroll
    for (int j = 0; j < 8; j++)
        hh[j] = __float2half(elu(acc[j] * inv + bi[j]));
    *(uint4*)(h1 + (size_t)w * C1 + lane * 8) = *(const uint4*)hh;
}

// ---------------- fused edge phase layer 2 + final linear head --------------
__global__ __launch_bounds__(256)
void edge_fused2_head_k(const int* __restrict__ rowptr, const int* __restrict__ deg,
                        const int* __restrict__ csrc,
                        const float* __restrict__ xl, const float* __restrict__ xr,
                        const float* __restrict__ att, const float* __restrict__ bias,
                        const float* __restrict__ Wlin, const float* __restrict__ blin,
                        float* __restrict__ out)
{
    __shared__ float Ws[HIDC][OUTDIM];      // 32x64 = 8 KB
    __shared__ float bs[OUTDIM];

    for (int i = threadIdx.x; i < HIDC * OUTDIM; i += blockDim.x)
        Ws[i >> 6][i & 63] = Wlin[i];
    if (threadIdx.x < OUTDIM) bs[threadIdx.x] = blin[threadIdx.x];
    __syncthreads();

    int w = (blockIdx.x * blockDim.x + threadIdx.x) >> 5;
    int lane = threadIdx.x & 31;
    if (w >= NN) return;

    float b = xr[(size_t)w * HIDC + lane];
    float t = att[lane];

    float acc = 0.f, den = 0.f;
    int start = rowptr[w];
    int dg    = deg[w];

    int s = (dg > 0) ? csrc[start] : 0;
    float a = xl[(size_t)s * HIDC + lane];

    for (int i = 0; i < dg; i++) {
        int snext = (i + 1 < dg) ? csrc[start + i + 1] : s;
        float n = xl[(size_t)snext * HIDC + lane];

        float p = lrelu(a + b) * t;
        p += __shfl_xor_sync(0xffffffffu, p, 16);
        p += __shfl_xor_sync(0xffffffffu, p, 8);
        p += __shfl_xor_sync(0xffffffffu, p, 4);
        p += __shfl_xor_sync(0xffffffffu, p, 2);
        p += __shfl_xor_sync(0xffffffffu, p, 1);
        float ex = __expf(p);
        den += ex;
        acc += ex * a;

        a = n;
    }
    float inv = 1.f / (den + 1e-16f);
    float hval = elu(acc * inv + bias[lane]);   // h2[w][lane]

    float o0 = bs[lane];
    float o1 = bs[lane + 32];
#pragma unroll
    for (int k = 0; k < HIDC; k++) {
        float v = __shfl_sync(0xffffffffu, hval, k);
        o0 = fmaf(v, Ws[k][lane],      o0);
        o1 = fmaf(v, Ws[k][lane + 32], o1);
    }
    out[(size_t)w * OUTDIM + lane]      = o0;
    out[(size_t)w * OUTDIM + lane + 32] = o1;
}

// ---------------- launch ------------------------------------------------------
extern "C" void kernel_launch(void* const* d_in, const int* in_sizes, int n_in,
                              void* d_out, int out_size)
{
    const float* x     = (const float*)d_in[0];
    const int*   ei    = (const int*)d_in[1];
    const float* W1l   = (const float*)d_in[2];
    const float* b1l   = (const float*)d_in[3];
    const float* W1r   = (const float*)d_in[4];
    const float* b1r   = (const float*)d_in[5];
    const float* att1  = (const float*)d_in[6];
    const float* bias1 = (const float*)d_in[7];
    const float* W2l   = (const float*)d_in[8];
    const float* b2l   = (const float*)d_in[9];
    const float* W2r   = (const float*)d_in[10];
    const float* b2r   = (const float*)d_in[11];
    const float* att2  = (const float*)d_in[12];
    const float* bias2 = (const float*)d_in[13];
    const float* Wlin  = (const float*)d_in[14];
    const float* blin  = (const float*)d_in[15];
    float* out = (float*)d_out;

    float *xl1, *xr1, *xl2, *xr2;
    int *deg, *rowptr, *cursor, *csrc, *bsums;
    __half *Ah, *Bh, *Bl, *H1, *B2h, *B2l;
    cudaGetSymbolAddress((void**)&xl1, g_xl1);
    cudaGetSymbolAddress((void**)&xr1, g_xr1);
    cudaGetSymbolAddress((void**)&xl2, g_xl2);
    cudaGetSymbolAddress((void**)&xr2, g_xr2);
    cudaGetSymbolAddress((void**)&deg,    g_deg);
    cudaGetSymbolAddress((void**)&rowptr, g_rowptr);
    cudaGetSymbolAddress((void**)&cursor, g_cursor);
    cudaGetSymbolAddress((void**)&csrc,   g_csrc);
    cudaGetSymbolAddress((void**)&bsums,  g_bsums);
    cudaGetSymbolAddress((void**)&Ah,  g_Ah);
    cudaGetSymbolAddress((void**)&Bh,  g_Bh);
    cudaGetSymbolAddress((void**)&Bl,  g_Bl);
    cudaGetSymbolAddress((void**)&H1,  g_H1);
    cudaGetSymbolAddress((void**)&B2h, g_B2h);
    cudaGetSymbolAddress((void**)&B2l, g_B2l);

    cudaFuncSetAttribute(gemm1_mma, cudaFuncAttributeMaxDynamicSharedMemorySize,
                         SMEM_BYTES);
    cudaFuncSetAttribute(gemm2_mma, cudaFuncAttributeMaxDynamicSharedMemorySize,
                         SMEM2_BYTES);

    const int TPB = 256;
    const int nScanBlocks = (NN + 255) / 256;       // 196

    // ---- stream fork: CSR build runs concurrently with conv + GEMM1 ----
    cudaStream_t s2;
    cudaStreamCreateWithFlags(&s2, cudaStreamNonBlocking);
    cudaEvent_t e1, e2;
    cudaEventCreateWithFlags(&e1, cudaEventDisableTiming);
    cudaEventCreateWithFlags(&e2, cudaEventDisableTiming);

    cudaEventRecord(e1, 0);
    cudaStreamWaitEvent(s2, e1, 0);

    // side stream: CSR pipeline + W2 conversion
    zero_deg_k<<<(NN + TPB - 1) / TPB, TPB, 0, s2>>>(deg);
    hist_k<<<(EE + TPB - 1) / TPB, TPB, 0, s2>>>(ei, deg);
    scan1_k<<<nScanBlocks, 256, 0, s2>>>(deg, rowptr, bsums);
    scan2_k<<<1, 256, 0, s2>>>(bsums, nScanBlocks);
    scan3_k<<<(NN + TPB - 1) / TPB, TPB, 0, s2>>>(rowptr, bsums, cursor);
    scatter_k<<<(EE + TPB - 1) / TPB, TPB, 0, s2>>>(ei, cursor, csrc);
    conv_w2_k<<<(NB2 * C1 + TPB - 1) / TPB, TPB, 0, s2>>>(W2l, W2r, B2h, B2l);
    cudaEventRecord(e2, s2);

    // main stream: conversions + GEMM1
    conv_x_k<<<(NN * INDIM + TPB - 1) / TPB, TPB>>>(x, Ah);
    conv_w_k<<<(NB * INDIM + TPB - 1) / TPB, TPB>>>(W1l, W1r, Bh, Bl);

    dim3 gg1(4, (NN + 127) / 128);
    gemm1_mma<<<gg1, TPB, SMEM_BYTES>>>(Ah, Bh, Bl, b1l, b1r, xl1, xr1);

    // join: edge phase needs both GEMM1 outputs and CSR
    cudaStreamWaitEvent(0, e2, 0);

    int eblocks = (NN * 32 + TPB - 1) / TPB;
    edge_fused1_k<<<eblocks, TPB>>>(rowptr, deg, csrc, xl1, xr1,
                                    att1, bias1, H1);

    gemm2_mma<<<(NN + 127) / 128, TPB, SMEM2_BYTES>>>(H1, B2h, B2l,
                                                      b2l, b2r, xl2, xr2);

    edge_fused2_head_k<<<eblocks, TPB>>>(rowptr, deg, csrc, xl2, xr2,
                                         att2, bias2, Wlin, blin, out);
}

// round 15
// speedup vs baseline: 1.2106x; 1.0672x over previous
#include <cuda_runtime.h>
#include <cuda_fp16.h>
#include <cstdint>

#define NN      50000
#define EE      800000
#define INDIM   256
#define HIDC    32
#define NHEADS  8
#define OUTDIM  64
#define C1      (NHEADS * HIDC)   // 256
#define NB      512               // total output cols of GEMM1 (Wl|Wr)
#define NB2     64                // total output cols of GEMM2 (W2l|W2r)
#define NEGSLOPE 0.2f

typedef unsigned long long u64;

// ---------------- scratch (device globals) ---------------------------------
__device__ float g_xl2[(size_t)NN * HIDC];
__device__ float g_xr2[(size_t)NN * HIDC];
__device__ int   g_deg   [NN];
__device__ int   g_rowptr[NN];
__device__ int   g_cursor[NN];
__device__ int   g_csrc  [EE];
__device__ int   g_bsums [256];
// fp16 operands
__device__ __align__(16) __half g_Ah  [(size_t)NN * INDIM];
__device__ __align__(16) __half g_Bh  [(size_t)NB * INDIM];
__device__ __align__(16) __half g_Bl  [(size_t)NB * INDIM];
__device__ __align__(16) __half g_xl1h[(size_t)NN * C1];   // GEMM1 out (fp16)
__device__ __align__(16) __half g_xr1h[(size_t)NN * C1];
__device__ __align__(16) __half g_H1  [(size_t)NN * C1];
__device__ __align__(16) __half g_B2h [(size_t)NB2 * C1];
__device__ __align__(16) __half g_B2l [(size_t)NB2 * C1];

// ---------------- helpers ---------------------------------------------------
__device__ __forceinline__ float lrelu(float v) { return v > 0.f ? v : NEGSLOPE * v; }
__device__ __forceinline__ float elu(float v)   { return v > 0.f ? v : expm1f(v); }

__device__ __forceinline__ uint32_t smem_u32(const void* p)
{
    uint32_t a;
    asm("{ .reg .u64 t; cvta.to.shared.u64 t, %1; cvt.u32.u64 %0, t; }"
        : "=r"(a) : "l"(p));
    return a;
}

// fp16 tensor-core mma (sm_80+ base)
#define MMA_F16(d, a0, a1, a2, a3, b0, b1)                                   \
    asm volatile(                                                            \
        "mma.sync.aligned.m16n8k16.row.col.f32.f16.f16.f32 "                 \
        "{%0,%1,%2,%3}, {%4,%5,%6,%7}, {%8,%9}, {%0,%1,%2,%3};"              \
        : "+f"((d)[0]), "+f"((d)[1]), "+f"((d)[2]), "+f"((d)[3])             \
        : "r"(a0), "r"(a1), "r"(a2), "r"(a3), "r"(b0), "r"(b1))

// ldmatrix (sm_75+ base)
#define LDSM_X4(r0, r1, r2, r3, addr)                                        \
    asm volatile("ldmatrix.sync.aligned.m8n8.x4.shared.b16 {%0,%1,%2,%3}, [%4];" \
                 : "=r"(r0), "=r"(r1), "=r"(r2), "=r"(r3) : "r"(addr))

// cp.async (sm_80+ base)
#define CP16(dst_u32, src_ptr) \
    asm volatile("cp.async.cg.shared.global [%0], [%1], 16;" \
                 :: "r"(dst_u32), "l"(src_ptr))
#define CP_COMMIT() asm volatile("cp.async.commit_group;" ::: "memory")
#define CP_WAIT(n)  asm volatile("cp.async.wait_group %0;" :: "n"(n) : "memory")

// ---------------- conversion kernels -----------------------------------------
__global__ void conv_x_k(const float* __restrict__ x, __half* __restrict__ Ah)
{
    size_t i = (size_t)blockIdx.x * blockDim.x + threadIdx.x;
    if (i >= (size_t)NN * INDIM) return;
    Ah[i] = __float2half(x[i]);
}

__global__ void conv_w_k(const float* __restrict__ W1l, const float* __restrict__ W1r,
                         __half* __restrict__ Bh, __half* __restrict__ Bl)
{
    int i = blockIdx.x * blockDim.x + threadIdx.x;
    if (i >= NB * INDIM) return;
    int n = i >> 8;
    int k = i & 255;
    float v = (n < C1) ? W1l[(size_t)k * C1 + n] : W1r[(size_t)k * C1 + (n - C1)];
    __half h = __float2half(v);
    Bh[i] = h;
    Bl[i] = __float2half(v - __half2float(h));
}

__global__ void conv_w2_k(const float* __restrict__ W2l, const float* __restrict__ W2r,
                          __half* __restrict__ B2h, __half* __restrict__ B2l)
{
    int i = blockIdx.x * blockDim.x + threadIdx.x;
    if (i >= NB2 * C1) return;
    int n = i >> 8;          // 0..63
    int k = i & 255;
    float v = (n < HIDC) ? W2l[(size_t)k * HIDC + n]
                         : W2r[(size_t)k * HIDC + (n - HIDC)];
    __half h = __float2half(v);
    B2h[i] = h;
    B2l[i] = __float2half(v - __half2float(h));
}

// ============================================================================
// GEMM1 via mma.sync fp16 2-product split; outputs fp16 (+bias) directly.
// CTA 128x128, K chunk 32, 8 warps 2x4. Stage 30720 B; 2 stages -> 3 CTAs/SM.
// ============================================================================
#define KCH    32
#define PAD2   40
#define T_ELEM (128 * PAD2)
#define T_BYTE (T_ELEM * 2)          // 10240
#define STG_BYTE (3 * T_BYTE)        // 30720
#define SMEM_BYTES (2 * STG_BYTE)    // 61440

__global__ __launch_bounds__(256)
void gemm1_mma(const __half* __restrict__ Ah,
               const __half* __restrict__ Bh, const __half* __restrict__ Bl,
               const float* __restrict__ bl1, const float* __restrict__ br1,
               __half* __restrict__ Xl, __half* __restrict__ Xr)
{
    extern __shared__ __half sm[];
    const uint32_t smb = smem_u32(sm);

    const int tid  = threadIdx.x;
    const int wid  = tid >> 5;
    const int lane = tid & 31;
    const int wm   = wid & 1;
    const int wn   = wid >> 1;
    const int rowBase = blockIdx.y * 128;
    const int colBase = blockIdx.x * 128;

    const int lr = lane >> 2;
    const int lc = (lane & 3) * 2;

    const int aRowOff = lane & 15;
    const int aKOff   = (lane >> 4) * 8;
    const int bGrp    = lane >> 3;
    const int bRowOff = (lane & 7) + (bGrp >> 1) * 8;
    const int bKOff   = (bGrp & 1) * 8;

#define LOAD_STAGE(stg, kOff) do {                                            \
    uint32_t sb = smb + (stg) * STG_BYTE;                                     \
    for (int idx = tid; idx < 512; idx += 256) {                              \
        int r  = idx >> 2;                                                    \
        int k8 = (idx & 3) * 8;                                               \
        uint32_t soff = (uint32_t)(r * (PAD2 * 2) + k8 * 2);                  \
        int ga = min(rowBase + r, NN - 1);                                    \
        int gb = colBase + r;                                                 \
        CP16(sb + soff,              Ah + (size_t)ga * INDIM + (kOff) + k8);  \
        CP16(sb + T_BYTE + soff,     Bh + (size_t)gb * INDIM + (kOff) + k8);  \
        CP16(sb + 2 * T_BYTE + soff, Bl + (size_t)gb * INDIM + (kOff) + k8);  \
    }                                                                         \
} while (0)

    float acc[4][4][4];
#pragma unroll
    for (int i = 0; i < 4; i++)
#pragma unroll
        for (int j = 0; j < 4; j++)
#pragma unroll
            for (int f = 0; f < 4; f++) acc[i][j][f] = 0.f;

    LOAD_STAGE(0, 0);
    CP_COMMIT();

    for (int kc = 0; kc < 8; kc++) {
        const int stg = kc & 1;
        if (kc + 1 < 8) {
            LOAD_STAGE((kc + 1) & 1, (kc + 1) * KCH);
            CP_COMMIT();
            CP_WAIT(1);
        } else {
            CP_WAIT(0);
        }
        __syncthreads();

        const uint32_t sA_u  = smb + stg * STG_BYTE;
        const uint32_t sBh_u = sA_u + T_BYTE;
        const uint32_t sBl_u = sA_u + 2 * T_BYTE;

#pragma unroll
        for (int ks = 0; ks < 2; ks++) {
            const int k0 = ks * 16;
            uint32_t bh[4][2], bl_[4][2];
#pragma unroll
            for (int jp = 0; jp < 4; jp += 2) {
                uint32_t baddr = (uint32_t)(((wn * 32 + jp * 8 + bRowOff) * PAD2
                                            + k0 + bKOff) * 2);
                LDSM_X4(bh[jp][0], bh[jp][1], bh[jp + 1][0], bh[jp + 1][1],
                        sBh_u + baddr);
                LDSM_X4(bl_[jp][0], bl_[jp][1], bl_[jp + 1][0], bl_[jp + 1][1],
                        sBl_u + baddr);
            }
#pragma unroll
            for (int i = 0; i < 4; i++) {
                uint32_t aaddr = (uint32_t)(((wm * 64 + i * 16 + aRowOff) * PAD2
                                            + k0 + aKOff) * 2);
                uint32_t a0, a1, a2, a3;
                LDSM_X4(a0, a1, a2, a3, sA_u + aaddr);
#pragma unroll
                for (int j = 0; j < 4; j++)
                    MMA_F16(acc[i][j], a0, a1, a2, a3, bh[j][0], bh[j][1]);
#pragma unroll
                for (int j = 0; j < 4; j++)
                    MMA_F16(acc[i][j], a0, a1, a2, a3, bl_[j][0], bl_[j][1]);
            }
        }
        __syncthreads();
    }

    // ---- epilogue: fp16 output (+bias) ----
    const bool isL = (colBase < C1);
    __half* X = isL ? Xl : Xr;
    const float* bs = isL ? bl1 : br1;
    const int cb = isL ? colBase : colBase - C1;
#pragma unroll
    for (int i = 0; i < 4; i++) {
        int r0 = rowBase + wm * 64 + i * 16 + lr;
#pragma unroll
        for (int j = 0; j < 4; j++) {
            int c = cb + wn * 32 + j * 8 + lc;
            float b0 = bs[c], b1 = bs[c + 1];
            if (r0 < NN) {
                __half2 o = __floats2half2_rn(acc[i][j][0] + b0, acc[i][j][1] + b1);
                *(__half2*)(X + (size_t)r0 * C1 + c) = o;
            }
            if (r0 + 8 < NN) {
                __half2 o = __floats2half2_rn(acc[i][j][2] + b0, acc[i][j][3] + b1);
                *(__half2*)(X + (size_t)(r0 + 8) * C1 + c) = o;
            }
        }
    }
#undef LOAD_STAGE
}

// ============================================================================
// GEMM2 via mma.sync fp16 2-product split. CTA 128x64, K=256 chunk 32.
// ============================================================================
#define B2_ROWS  64
#define B2_ELEM  (B2_ROWS * PAD2)     // 2560
#define B2_BYTE  (B2_ELEM * 2)        // 5120
#define STG2_BYTE (T_BYTE + 2 * B2_BYTE)       // 20480
#define SMEM2_BYTES (2 * STG2_BYTE)            // 40960

__global__ __launch_bounds__(256)
void gemm2_mma(const __half* __restrict__ Ah,
               const __half* __restrict__ Bh, const __half* __restrict__ Bl,
               const float* __restrict__ bl2, const float* __restrict__ br2,
               float* __restrict__ Xl, float* __restrict__ Xr)
{
    extern __shared__ __half sm[];
    const uint32_t smb = smem_u32(sm);

    const int tid  = threadIdx.x;
    const int wid  = tid >> 5;
    const int lane = tid & 31;
    const int wm   = wid & 1;
    const int wn   = wid >> 1;
    const int rowBase = blockIdx.x * 128;

    const int lr = lane >> 2;
    const int lc = (lane & 3) * 2;

    const int aRowOff = lane & 15;
    const int aKOff   = (lane >> 4) * 8;
    const int bGrp    = lane >> 3;
    const int bRowOff = (lane & 7) + (bGrp >> 1) * 8;
    const int bKOff   = (bGrp & 1) * 8;

#define LOAD_STAGE2(stg, kOff) do {                                           \
    uint32_t sb = smb + (stg) * STG2_BYTE;                                    \
    for (int idx = tid; idx < 512; idx += 256) {                              \
        int r  = idx >> 2;                                                    \
        int k8 = (idx & 3) * 8;                                               \
        uint32_t soff = (uint32_t)(r * (PAD2 * 2) + k8 * 2);                  \
        int ga = min(rowBase + r, NN - 1);                                    \
        CP16(sb + soff, Ah + (size_t)ga * C1 + (kOff) + k8);                  \
    }                                                                         \
    {                                                                         \
        int r  = tid >> 2;                                                    \
        int k8 = (tid & 3) * 8;                                               \
        uint32_t soff = (uint32_t)(r * (PAD2 * 2) + k8 * 2);                  \
        CP16(sb + T_BYTE + soff,           Bh + (size_t)r * C1 + (kOff) + k8);\
        CP16(sb + T_BYTE + B2_BYTE + soff, Bl + (size_t)r * C1 + (kOff) + k8);\
    }                                                                         \
} while (0)

    float acc[4][2][4];
#pragma unroll
    for (int i = 0; i < 4; i++)
#pragma unroll
        for (int j = 0; j < 2; j++)
#pragma unroll
            for (int f = 0; f < 4; f++) acc[i][j][f] = 0.f;

    LOAD_STAGE2(0, 0);
    CP_COMMIT();

    for (int kc = 0; kc < 8; kc++) {
        const int stg = kc & 1;
        if (kc + 1 < 8) {
            LOAD_STAGE2((kc + 1) & 1, (kc + 1) * KCH);
            CP_COMMIT();
            CP_WAIT(1);
        } else {
            CP_WAIT(0);
        }
        __syncthreads();

        const uint32_t sA_u  = smb + stg * STG2_BYTE;
        const uint32_t sBh_u = sA_u + T_BYTE;
        const uint32_t sBl_u = sBh_u + B2_BYTE;

#pragma unroll
        for (int ks = 0; ks < 2; ks++) {
            const int k0 = ks * 16;
            uint32_t bh[2][2], bl_[2][2];
            {
                uint32_t baddr = (uint32_t)(((wn * 16 + bRowOff) * PAD2
                                            + k0 + bKOff) * 2);
                LDSM_X4(bh[0][0], bh[0][1], bh[1][0], bh[1][1], sBh_u + baddr);
                LDSM_X4(bl_[0][0], bl_[0][1], bl_[1][0], bl_[1][1], sBl_u + baddr);
            }
#pragma unroll
            for (int i = 0; i < 4; i++) {
                uint32_t aaddr = (uint32_t)(((wm * 64 + i * 16 + aRowOff) * PAD2
                                            + k0 + aKOff) * 2);
                uint32_t a0, a1, a2, a3;
                LDSM_X4(a0, a1, a2, a3, sA_u + aaddr);
#pragma unroll
                for (int j = 0; j < 2; j++)
                    MMA_F16(acc[i][j], a0, a1, a2, a3, bh[j][0], bh[j][1]);
#pragma unroll
                for (int j = 0; j < 2; j++)
                    MMA_F16(acc[i][j], a0, a1, a2, a3, bl_[j][0], bl_[j][1]);
            }
        }
        __syncthreads();
    }

    const bool isL = (wn < 2);
    float* X = isL ? Xl : Xr;
    const float* bs = isL ? bl2 : br2;
    const int cb = isL ? wn * 16 : wn * 16 - HIDC;
#pragma unroll
    for (int i = 0; i < 4; i++) {
        int r0 = rowBase + wm * 64 + i * 16 + lr;
#pragma unroll
        for (int j = 0; j < 2; j++) {
            int c = cb + j * 8 + lc;
            float b0 = bs[c], b1 = bs[c + 1];
            if (r0 < NN) {
                float2 o = make_float2(acc[i][j][0] + b0, acc[i][j][1] + b1);
                *(float2*)(X + (size_t)r0 * HIDC + c) = o;
            }
            if (r0 + 8 < NN) {
                float2 o = make_float2(acc[i][j][2] + b0, acc[i][j][3] + b1);
                *(float2*)(X + (size_t)(r0 + 8) * HIDC + c) = o;
            }
        }
    }
#undef LOAD_STAGE2
}

// ---------------- CSR construction ------------------------------------------
__global__ void zero_deg_k(int* __restrict__ deg)
{
    int i = blockIdx.x * blockDim.x + threadIdx.x;
    if (i < NN) deg[i] = 0;
}

__global__ void hist_k(const int* __restrict__ ei, int* __restrict__ deg)
{
    int e = blockIdx.x * blockDim.x + threadIdx.x;
    if (e < EE) atomicAdd(&deg[ei[EE + e]], 1);
}

__global__ void scan1_k(const int* __restrict__ deg, int* __restrict__ rowptr,
                        int* __restrict__ bsums)
{
    __shared__ int sh[256];
    int tid = threadIdx.x;
    int i = blockIdx.x * 256 + tid;
    int v = (i < NN) ? deg[i] : 0;
    sh[tid] = v;
    __syncthreads();
#pragma unroll
    for (int off = 1; off < 256; off <<= 1) {
        int t = (tid >= off) ? sh[tid - off] : 0;
        __syncthreads();
        sh[tid] += t;
        __syncthreads();
    }
    if (i < NN) rowptr[i] = sh[tid] - v;
    if (tid == 255) bsums[blockIdx.x] = sh[255];
}

__global__ void scan2_k(int* __restrict__ bsums, int nb)
{
    __shared__ int sh[256];
    int tid = threadIdx.x;
    int v = (tid < nb) ? bsums[tid] : 0;
    sh[tid] = v;
    __syncthreads();
#pragma unroll
    for (int off = 1; off < 256; off <<= 1) {
        int t = (tid >= off) ? sh[tid - off] : 0;
        __syncthreads();
        sh[tid] += t;
        __syncthreads();
    }
    if (tid < nb) bsums[tid] = sh[tid] - v;
}

__global__ void scan3_k(int* __restrict__ rowptr, const int* __restrict__ bsums,
                        int* __restrict__ cursor)
{
    int i = blockIdx.x * blockDim.x + threadIdx.x;
    if (i >= NN) return;
    int r = rowptr[i] + bsums[i >> 8];
    rowptr[i] = r;
    cursor[i] = r;
}

__global__ void scatter_k(const int* __restrict__ ei, int* __restrict__ cursor,
                          int* __restrict__ csrc)
{
    int e = blockIdx.x * blockDim.x + threadIdx.x;
    if (e >= EE) return;
    int d = ei[EE + e];
    int pos = atomicAdd(&cursor[d], 1);
    csrc[pos] = ei[e];
}

// ---------------- fused GATv2 edge phase, layer 1 (fp16 gathers) ------------
__global__ __launch_bounds__(256)
void edge_fused1_k(const int* __restrict__ rowptr, const int* __restrict__ deg,
                   const int* __restrict__ csrc,
                   const __half* __restrict__ xl, const __half* __restrict__ xr,
                   const float* __restrict__ att, const float* __restrict__ bias,
                   __half* __restrict__ h1)
{
    int w = (blockIdx.x * blockDim.x + threadIdx.x) >> 5;
    if (w >= NN) return;
    int lane = threadIdx.x & 31;

    // xr row (8 halves -> 2 float4)
    float4 b0, b1;
    {
        uint4 raw = *(const uint4*)(xr + (size_t)w * C1 + lane * 8);
        __half2 h0 = *(__half2*)&raw.x, h1_ = *(__half2*)&raw.y;
        __half2 h2 = *(__half2*)&raw.z, h3 = *(__half2*)&raw.w;
        float2 f0 = __half22float2(h0), f1 = __half22float2(h1_);
        float2 f2 = __half22float2(h2), f3 = __half22float2(h3);
        b0 = make_float4(f0.x, f0.y, f1.x, f1.y);
        b1 = make_float4(f2.x, f2.y, f3.x, f3.y);
    }
    const float4* pt = reinterpret_cast<const float4*>(att + lane * 8);
    float4 t0 = pt[0], t1 = pt[1];

    float acc[8] = {};
    float den = 0.f;

    int start = rowptr[w];
    int dg    = deg[w];

    int s = (dg > 0) ? csrc[start] : 0;
    uint4 rawA = *(const uint4*)(xl + (size_t)s * C1 + lane * 8);

    for (int i = 0; i < dg; i++) {
        int snext = (i + 1 < dg) ? csrc[start + i + 1] : s;
        uint4 rawN = *(const uint4*)(xl + (size_t)snext * C1 + lane * 8);

        float2 f0 = __half22float2(*(__half2*)&rawA.x);
        float2 f1 = __half22float2(*(__half2*)&rawA.y);
        float2 f2 = __half22float2(*(__half2*)&rawA.z);
        float2 f3 = __half22float2(*(__half2*)&rawA.w);
        float4 a0 = make_float4(f0.x, f0.y, f1.x, f1.y);
        float4 a1 = make_float4(f2.x, f2.y, f3.x, f3.y);

        float p = lrelu(a0.x + b0.x) * t0.x + lrelu(a0.y + b0.y) * t0.y
                + lrelu(a0.z + b0.z) * t0.z + lrelu(a0.w + b0.w) * t0.w
                + lrelu(a1.x + b1.x) * t1.x + lrelu(a1.y + b1.y) * t1.y
                + lrelu(a1.z + b1.z) * t1.z + lrelu(a1.w + b1.w) * t1.w;
        p += __shfl_xor_sync(0xffffffffu, p, 1);
        p += __shfl_xor_sync(0xffffffffu, p, 2);
        float ex = __expf(p);
        den += ex;
        acc[0] += ex * a0.x; acc[1] += ex * a0.y;
        acc[2] += ex * a0.z; acc[3] += ex * a0.w;
        acc[4] += ex * a1.x; acc[5] += ex * a1.y;
        acc[6] += ex * a1.z; acc[7] += ex * a1.w;

        rawA = rawN;
    }

    float inv = 1.f / (den + 1e-16f);
    const float* bi = bias + lane * 8;
    __half hh[8];
#pragma unroll
    for (int j = 0; j < 8; j++)
        hh[j] = __float2half(elu(acc[j] * inv + bi[j]));
    *(uint4*)(h1 + (size_t)w * C1 + lane * 8) = *(const uint4*)hh;
}

// ---------------- fused edge phase layer 2 + final linear head --------------
__global__ __launch_bounds__(256)
void edge_fused2_head_k(const int* __restrict__ rowptr, const int* __restrict__ deg,
                        const int* __restrict__ csrc,
                        const float* __restrict__ xl, const float* __restrict__ xr,
                        const float* __restrict__ att, const float* __restrict__ bias,
                        const float* __restrict__ Wlin, const float* __restrict__ blin,
                        float* __restrict__ out)
{
    __shared__ float Ws[HIDC][OUTDIM];      // 32x64 = 8 KB
    __shared__ float bs[OUTDIM];

    for (int i = threadIdx.x; i < HIDC * OUTDIM; i += blockDim.x)
        Ws[i >> 6][i & 63] = Wlin[i];
    if (threadIdx.x < OUTDIM) bs[threadIdx.x] = blin[threadIdx.x];
    __syncthreads();

    int w = (blockIdx.x * blockDim.x + threadIdx.x) >> 5;
    int lane = threadIdx.x & 31;
    if (w >= NN) return;

    float b = xr[(size_t)w * HIDC + lane];
    float t = att[lane];

    float acc = 0.f, den = 0.f;
    int start = rowptr[w];
    int dg    = deg[w];

    int s = (dg > 0) ? csrc[start] : 0;
    float a = xl[(size_t)s * HIDC + lane];

    for (int i = 0; i < dg; i++) {
        int snext = (i + 1 < dg) ? csrc[start + i + 1] : s;
        float n = xl[(size_t)snext * HIDC + lane];

        float p = lrelu(a + b) * t;
        p += __shfl_xor_sync(0xffffffffu, p, 16);
        p += __shfl_xor_sync(0xffffffffu, p, 8);
        p += __shfl_xor_sync(0xffffffffu, p, 4);
        p += __shfl_xor_sync(0xffffffffu, p, 2);
        p += __shfl_xor_sync(0xffffffffu, p, 1);
        float ex = __expf(p);
        den += ex;
        acc += ex * a;

        a = n;
    }
    float inv = 1.f / (den + 1e-16f);
    float hval = elu(acc * inv + bias[lane]);   // h2[w][lane]

    float o0 = bs[lane];
    float o1 = bs[lane + 32];
#pragma unroll
    for (int k = 0; k < HIDC; k++) {
        float v = __shfl_sync(0xffffffffu, hval, k);
        o0 = fmaf(v, Ws[k][lane],      o0);
        o1 = fmaf(v, Ws[k][lane + 32], o1);
    }
    out[(size_t)w * OUTDIM + lane]      = o0;
    out[(size_t)w * OUTDIM + lane + 32] = o1;
}

// ---------------- launch ------------------------------------------------------
extern "C" void kernel_launch(void* const* d_in, const int* in_sizes, int n_in,
                              void* d_out, int out_size)
{
    const float* x     = (const float*)d_in[0];
    const int*   ei    = (const int*)d_in[1];
    const float* W1l   = (const float*)d_in[2];
    const float* b1l   = (const float*)d_in[3];
    const float* W1r   = (const float*)d_in[4];
    const float* b1r   = (const float*)d_in[5];
    const float* att1  = (const float*)d_in[6];
    const float* bias1 = (const float*)d_in[7];
    const float* W2l   = (const float*)d_in[8];
    const float* b2l   = (const float*)d_in[9];
    const float* W2r   = (const float*)d_in[10];
    const float* b2r   = (const float*)d_in[11];
    const float* att2  = (const float*)d_in[12];
    const float* bias2 = (const float*)d_in[13];
    const float* Wlin  = (const float*)d_in[14];
    const float* blin  = (const float*)d_in[15];
    float* out = (float*)d_out;

    float *xl2, *xr2;
    int *deg, *rowptr, *cursor, *csrc, *bsums;
    __half *Ah, *Bh, *Bl, *xl1h, *xr1h, *H1, *B2h, *B2l;
    cudaGetSymbolAddress((void**)&xl2, g_xl2);
    cudaGetSymbolAddress((void**)&xr2, g_xr2);
    cudaGetSymbolAddress((void**)&deg,    g_deg);
    cudaGetSymbolAddress((void**)&rowptr, g_rowptr);
    cudaGetSymbolAddress((void**)&cursor, g_cursor);
    cudaGetSymbolAddress((void**)&csrc,   g_csrc);
    cudaGetSymbolAddress((void**)&bsums,  g_bsums);
    cudaGetSymbolAddress((void**)&Ah,   g_Ah);
    cudaGetSymbolAddress((void**)&Bh,   g_Bh);
    cudaGetSymbolAddress((void**)&Bl,   g_Bl);
    cudaGetSymbolAddress((void**)&xl1h, g_xl1h);
    cudaGetSymbolAddress((void**)&xr1h, g_xr1h);
    cudaGetSymbolAddress((void**)&H1,   g_H1);
    cudaGetSymbolAddress((void**)&B2h,  g_B2h);
    cudaGetSymbolAddress((void**)&B2l,  g_B2l);

    cudaFuncSetAttribute(gemm1_mma, cudaFuncAttributeMaxDynamicSharedMemorySize,
                         SMEM_BYTES);
    cudaFuncSetAttribute(gemm2_mma, cudaFuncAttributeMaxDynamicSharedMemorySize,
                         SMEM2_BYTES);

    const int TPB = 256;
    const int nScanBlocks = (NN + 255) / 256;       // 196

    // ---- stream fork: CSR build runs concurrently with conv + GEMM1 ----
    cudaStream_t s2;
    cudaStreamCreateWithFlags(&s2, cudaStreamNonBlocking);
    cudaEvent_t e1, e2;
    cudaEventCreateWithFlags(&e1, cudaEventDisableTiming);
    cudaEventCreateWithFlags(&e2, cudaEventDisableTiming);

    cudaEventRecord(e1, 0);
    cudaStreamWaitEvent(s2, e1, 0);

    // side stream: CSR pipeline + W2 conversion
    zero_deg_k<<<(NN + TPB - 1) / TPB, TPB, 0, s2>>>(deg);
    hist_k<<<(EE + TPB - 1) / TPB, TPB, 0, s2>>>(ei, deg);
    scan1_k<<<nScanBlocks, 256, 0, s2>>>(deg, rowptr, bsums);
    scan2_k<<<1, 256, 0, s2>>>(bsums, nScanBlocks);
    scan3_k<<<(NN + TPB - 1) / TPB, TPB, 0, s2>>>(rowptr, bsums, cursor);
    scatter_k<<<(EE + TPB - 1) / TPB, TPB, 0, s2>>>(ei, cursor, csrc);
    conv_w2_k<<<(NB2 * C1 + TPB - 1) / TPB, TPB, 0, s2>>>(W2l, W2r, B2h, B2l);
    cudaEventRecord(e2, s2);

    // main stream: conversions + GEMM1
    conv_x_k<<<(NN * INDIM + TPB - 1) / TPB, TPB>>>(x, Ah);
    conv_w_k<<<(NB * INDIM + TPB - 1) / TPB, TPB>>>(W1l, W1r, Bh, Bl);

    dim3 gg1(4, (NN + 127) / 128);
    gemm1_mma<<<gg1, TPB, SMEM_BYTES>>>(Ah, Bh, Bl, b1l, b1r, xl1h, xr1h);

    // join: edge phase needs both GEMM1 outputs and CSR
    cudaStreamWaitEvent(0, e2, 0);

    int eblocks = (NN * 32 + TPB - 1) / TPB;
    edge_fused1_k<<<eblocks, TPB>>>(rowptr, deg, csrc, xl1h, xr1h,
                                    att1, bias1, H1);

    gemm2_mma<<<(NN + 127) / 128, TPB, SMEM2_BYTES>>>(H1, B2h, B2l,
                                                      b2l, b2r, xl2, xr2);

    edge_fused2_head_k<<<eblocks, TPB>>>(rowptr, deg, csrc, xl2, xr2,
                                         att2, bias2, Wlin, blin, out);
}